// round 1
// baseline (speedup 1.0000x reference)
#include <cuda_runtime.h>
#include <math.h>

// Problem shape (fixed by the dataset)
#define Bc 4
#define Sc 2048
#define Dc 1024
#define Mc (Bc * Sc)

#define BM 128
#define BN 128
#define BK 8
#define TM 8
#define TN 8
#define NTHREADS 256

enum { EPI_NONE = 0, EPI_BIAS = 1, EPI_BIAS_RES = 2, EPI_BIAS_RELU = 3 };

// ---------------- scratch (no allocation allowed -> device globals) ---------
__device__ float g_xn[(size_t)Mc * Dc];   // LN1 output
__device__ float g_q [(size_t)Mc * Dc];
__device__ float g_k [(size_t)Mc * Dc];
__device__ float g_v [(size_t)Mc * Dc];
__device__ float g_s [(size_t)Bc * Sc * Sc]; // scores / attn (in-place softmax)
__device__ float g_ao[(size_t)Mc * Dc];   // attn @ V
__device__ float g_h [(size_t)Mc * Dc];   // attention block output + x
__device__ float g_m [(size_t)Mc * Dc];   // LN2 output
__device__ float g_f [(size_t)Mc * Dc];   // relu(m@w1+b1)

// ---------------- SGEMM 128x128x8, fp32, double-buffered --------------------
// C[M,N] = alpha * A[M,K] @ (TRANS_B ? B[N,K]^T : B[K,N])  (+ bias / res / relu)
template <bool TRANS_B, int EPI, bool CSKIP, bool CKLIM>
__global__ __launch_bounds__(NTHREADS)
void sgemm(const float* __restrict__ A, const float* __restrict__ Bm,
           const float* __restrict__ bias, const float* __restrict__ res,
           float* __restrict__ C, int M, int N, int K, float alpha,
           long sA, long sB, long sC)
{
    const int brow = blockIdx.y * BM;
    const int bcol = blockIdx.x * BN;
    if (CSKIP) {
        // causal: tile entirely above the diagonal -> never read by softmax
        if (bcol > brow + (BM - 1)) return;
    }

    const int z = blockIdx.z;
    A  += (long)z * sA;
    Bm += (long)z * sB;
    C  += (long)z * sC;

    int kEnd = K;
    if (CKLIM) kEnd = min(K, brow + BM);  // attn rows have zeros past the diag

    __shared__ float As[2][BK][BM];
    __shared__ float Bs[2][BK][BN];

    const int tid  = threadIdx.x;
    const int aRow = tid >> 1;          // 0..127
    const int aCol = (tid & 1) << 2;    // 0 or 4
    const int bRow = tid >> 5;          // 0..7
    const int bCol = (tid & 31) << 2;   // 0..124

    const int ty = (tid >> 4) * TM;
    const int tx = (tid & 15) * TN;

    const int ldA = K;
    const int ldB = TRANS_B ? K : N;

    float acc[TM][TN];
#pragma unroll
    for (int i = 0; i < TM; ++i)
#pragma unroll
        for (int j = 0; j < TN; ++j) acc[i][j] = 0.f;

    auto load_tiles = [&](int k0, int buf) {
        float4 av = *reinterpret_cast<const float4*>(
            A + (long)(brow + aRow) * ldA + k0 + aCol);
        As[buf][aCol + 0][aRow] = av.x;
        As[buf][aCol + 1][aRow] = av.y;
        As[buf][aCol + 2][aRow] = av.z;
        As[buf][aCol + 3][aRow] = av.w;
        if (TRANS_B) {
            float4 bv = *reinterpret_cast<const float4*>(
                Bm + (long)(bcol + aRow) * ldB + k0 + aCol);
            Bs[buf][aCol + 0][aRow] = bv.x;
            Bs[buf][aCol + 1][aRow] = bv.y;
            Bs[buf][aCol + 2][aRow] = bv.z;
            Bs[buf][aCol + 3][aRow] = bv.w;
        } else {
            float4 bv = *reinterpret_cast<const float4*>(
                Bm + (long)(k0 + bRow) * ldB + bcol + bCol);
            *reinterpret_cast<float4*>(&Bs[buf][bRow][bCol]) = bv;
        }
    };

    load_tiles(0, 0);
    __syncthreads();

    const int nk = kEnd / BK;
    for (int t = 0; t < nk; ++t) {
        const int cb = t & 1;
        if (t + 1 < nk) load_tiles((t + 1) * BK, cb ^ 1);
#pragma unroll
        for (int kk = 0; kk < BK; ++kk) {
            float af[TM], bf[TN];
#pragma unroll
            for (int i = 0; i < TM; i += 4)
                *reinterpret_cast<float4*>(&af[i]) =
                    *reinterpret_cast<const float4*>(&As[cb][kk][ty + i]);
#pragma unroll
            for (int j = 0; j < TN; j += 4)
                *reinterpret_cast<float4*>(&bf[j]) =
                    *reinterpret_cast<const float4*>(&Bs[cb][kk][tx + j]);
#pragma unroll
            for (int i = 0; i < TM; ++i)
#pragma unroll
                for (int j = 0; j < TN; ++j)
                    acc[i][j] += af[i] * bf[j];
        }
        __syncthreads();
    }

    float bfr[TN];
    if (EPI != EPI_NONE) {
#pragma unroll
        for (int j = 0; j < TN; j += 4)
            *reinterpret_cast<float4*>(&bfr[j]) =
                *reinterpret_cast<const float4*>(bias + bcol + tx + j);
    }

#pragma unroll
    for (int i = 0; i < TM; ++i) {
        const long r = brow + ty + i;
#pragma unroll
        for (int j = 0; j < TN; j += 4) {
            float4 rv;
            if (EPI == EPI_BIAS_RES)
                rv = *reinterpret_cast<const float4*>(res + r * N + bcol + tx + j);
            float4 v;
            float* vp = &v.x;
#pragma unroll
            for (int u = 0; u < 4; ++u) {
                float vv = acc[i][j + u] * alpha;
                if (EPI == EPI_BIAS)       vv += bfr[j + u];
                if (EPI == EPI_BIAS_RELU)  vv = fmaxf(vv + bfr[j + u], 0.f);
                if (EPI == EPI_BIAS_RES)   vv += bfr[j + u] + (&rv.x)[u];
                vp[u] = vv;
            }
            *reinterpret_cast<float4*>(C + r * N + bcol + tx + j) = v;
        }
    }
}

// ---------------- LayerNorm (torch-style: unbiased std, eps on std) ---------
__global__ __launch_bounds__(NTHREADS)
void layernorm_k(const float* __restrict__ x, const float* __restrict__ gamma,
                 const float* __restrict__ beta, float* __restrict__ y)
{
    const long row = blockIdx.x;
    const float* xr = x + row * Dc;
    float* yr = y + row * Dc;
    __shared__ float red[NTHREADS];
    const int tid = threadIdx.x;

    float s = 0.f;
    for (int i = tid; i < Dc; i += NTHREADS) s += xr[i];
    red[tid] = s; __syncthreads();
    for (int st = NTHREADS / 2; st > 0; st >>= 1) {
        if (tid < st) red[tid] += red[tid + st];
        __syncthreads();
    }
    const float mean = red[0] / (float)Dc;
    __syncthreads();

    float v = 0.f;
    for (int i = tid; i < Dc; i += NTHREADS) {
        const float d = xr[i] - mean;
        v += d * d;
    }
    red[tid] = v; __syncthreads();
    for (int st = NTHREADS / 2; st > 0; st >>= 1) {
        if (tid < st) red[tid] += red[tid + st];
        __syncthreads();
    }
    const float var = red[0] / (float)(Dc - 1);   // ddof=1
    const float inv = 1.f / (sqrtf(var) + 1e-6f); // eps on std
    for (int i = tid; i < Dc; i += NTHREADS)
        yr[i] = gamma[i] * (xr[i] - mean) * inv + beta[i];
}

// ---------------- causal row softmax (in place, zeros above diagonal) -------
__global__ __launch_bounds__(NTHREADS)
void softmax_causal(float* __restrict__ sc)
{
    const int m = blockIdx.x;
    const int b = blockIdx.y;
    float* row = sc + ((long)b * Sc + m) * (long)Sc;
    const int n = m + 1;
    __shared__ float red[NTHREADS];
    const int tid = threadIdx.x;

    float lmax = -1e30f;
    for (int i = tid; i < n; i += NTHREADS) lmax = fmaxf(lmax, row[i]);
    red[tid] = lmax; __syncthreads();
    for (int st = NTHREADS / 2; st > 0; st >>= 1) {
        if (tid < st) red[tid] = fmaxf(red[tid], red[tid + st]);
        __syncthreads();
    }
    const float gmax = red[0];
    __syncthreads();

    float lsum = 0.f;
    for (int i = tid; i < n; i += NTHREADS) lsum += __expf(row[i] - gmax);
    red[tid] = lsum; __syncthreads();
    for (int st = NTHREADS / 2; st > 0; st >>= 1) {
        if (tid < st) red[tid] += red[tid + st];
        __syncthreads();
    }
    const float inv = 1.f / red[0];

    for (int i = tid; i < n; i += NTHREADS) row[i] = __expf(row[i] - gmax) * inv;
    for (int i = n + tid; i < Sc; i += NTHREADS) row[i] = 0.f;
}

// ---------------------------------------------------------------------------
extern "C" void kernel_launch(void* const* d_in, const int* in_sizes, int n_in,
                              void* d_out, int out_size)
{
    const float* x   = (const float*)d_in[0];
    const float* wq  = (const float*)d_in[1];
    const float* bq  = (const float*)d_in[2];
    const float* wk  = (const float*)d_in[3];
    const float* bk  = (const float*)d_in[4];
    const float* wv  = (const float*)d_in[5];
    const float* bv  = (const float*)d_in[6];
    const float* wo  = (const float*)d_in[7];
    const float* bo  = (const float*)d_in[8];
    const float* w1  = (const float*)d_in[9];
    const float* b1  = (const float*)d_in[10];
    const float* w2  = (const float*)d_in[11];
    const float* b2  = (const float*)d_in[12];
    const float* g1  = (const float*)d_in[13];
    const float* be1 = (const float*)d_in[14];
    const float* g2  = (const float*)d_in[15];
    const float* be2 = (const float*)d_in[16];
    float* out = (float*)d_out;

    float *xn, *q, *k, *v, *s, *ao, *h, *m, *f;
    cudaGetSymbolAddress((void**)&xn, g_xn);
    cudaGetSymbolAddress((void**)&q,  g_q);
    cudaGetSymbolAddress((void**)&k,  g_k);
    cudaGetSymbolAddress((void**)&v,  g_v);
    cudaGetSymbolAddress((void**)&s,  g_s);
    cudaGetSymbolAddress((void**)&ao, g_ao);
    cudaGetSymbolAddress((void**)&h,  g_h);
    cudaGetSymbolAddress((void**)&m,  g_m);
    cudaGetSymbolAddress((void**)&f,  g_f);

    const float inv_sqrt_s = 1.0f / sqrtf((float)Sc);

    const dim3 blk(NTHREADS);
    const dim3 gProj(Dc / BN, Mc / BM, 1);        // 8 x 64
    const dim3 gScore(Sc / BN, Sc / BM, Bc);      // 16 x 16 x 4
    const dim3 gAV(Dc / BN, Sc / BM, Bc);         // 8 x 16 x 4

    // 1) LN1
    layernorm_k<<<Mc, blk>>>(x, g1, be1, xn);

    // 2) Q, K, V projections (bias fused)
    sgemm<false, EPI_BIAS, false, false><<<gProj, blk>>>(
        xn, wq, bq, nullptr, q, Mc, Dc, Dc, 1.f, 0, 0, 0);
    sgemm<false, EPI_BIAS, false, false><<<gProj, blk>>>(
        xn, wk, bk, nullptr, k, Mc, Dc, Dc, 1.f, 0, 0, 0);
    sgemm<false, EPI_BIAS, false, false><<<gProj, blk>>>(
        xn, wv, bv, nullptr, v, Mc, Dc, Dc, 1.f, 0, 0, 0);

    // 3) scores = (q @ k^T) / sqrt(S), causal tiles skipped
    sgemm<true, EPI_NONE, true, false><<<gScore, blk>>>(
        q, k, nullptr, nullptr, s, Sc, Sc, Dc, inv_sqrt_s,
        (long)Sc * Dc, (long)Sc * Dc, (long)Sc * Sc);

    // 4) causal softmax in place (zeros above diagonal)
    softmax_causal<<<dim3(Sc, Bc), blk>>>(s);

    // 5) attn @ V, with per-row-block K limit (past-diag weights are zero)
    sgemm<false, EPI_NONE, false, true><<<gAV, blk>>>(
        s, v, nullptr, nullptr, ao, Sc, Dc, Sc, 1.f,
        (long)Sc * Sc, (long)Sc * Dc, (long)Sc * Dc);

    // 6) h = ao @ wo + bo + x
    sgemm<false, EPI_BIAS_RES, false, false><<<gProj, blk>>>(
        ao, wo, bo, x, h, Mc, Dc, Dc, 1.f, 0, 0, 0);

    // 7) LN2
    layernorm_k<<<Mc, blk>>>(h, g2, be2, m);

    // 8) f = relu(m @ w1 + b1)
    sgemm<false, EPI_BIAS_RELU, false, false><<<gProj, blk>>>(
        m, w1, b1, nullptr, f, Mc, Dc, Dc, 1.f, 0, 0, 0);

    // 9) out = f @ w2 + b2 + h
    sgemm<false, EPI_BIAS_RES, false, false><<<gProj, blk>>>(
        f, w2, b2, h, out, Mc, Dc, Dc, 1.f, 0, 0, 0);
}

// round 3
// speedup vs baseline: 1.9656x; 1.9656x over previous
#include <cuda_runtime.h>
#include <cuda_bf16.h>
#include <math.h>
#include <stdint.h>

// ---------------- problem shape ----------------
#define Bc 4
#define Sc 2048
#define Dc 1024
#define Mc (Bc * Sc)
#define K3D (3 * Dc)   // 3072 augmented-K for D-sized contractions
#define K3S (3 * Sc)   // 6144 augmented-K for S-sized contractions

// ---------------- scratch (device globals; no allocation allowed) ----------
__device__ __align__(256) __nv_bfloat16 g_xn2[(size_t)Mc * K3D];
__device__ __align__(256) __nv_bfloat16 g_q2 [(size_t)Mc * K3D];
__device__ __align__(256) __nv_bfloat16 g_k2 [(size_t)Mc * K3D];
__device__ __align__(256) float         g_v  [(size_t)Mc * Dc];
__device__ __align__(256) __nv_bfloat16 g_vt2[(size_t)Bc * Dc * K3S];
__device__ __align__(256) float         g_s  [(size_t)Bc * Sc * Sc];
__device__ __align__(256) __nv_bfloat16 g_a2 [(size_t)Mc * K3S];
__device__ __align__(256) __nv_bfloat16 g_ao2[(size_t)Mc * K3D];
__device__ __align__(256) float         g_h  [(size_t)Mc * Dc];
__device__ __align__(256) __nv_bfloat16 g_m2 [(size_t)Mc * K3D];
__device__ __align__(256) __nv_bfloat16 g_f2 [(size_t)Mc * K3D];
__device__ __align__(256) __nv_bfloat16 g_wt2[6][(size_t)Dc * K3D];

// ---------------- PTX helpers ----------------
__device__ __forceinline__ uint32_t s2u(const void* p) {
    uint32_t a;
    asm("{ .reg .u64 t; cvta.to.shared.u64 t, %1; cvt.u32.u64 %0, t; }"
        : "=r"(a) : "l"(p));
    return a;
}
__device__ __forceinline__ void cp16(uint32_t s, const void* g) {
    asm volatile("cp.async.cg.shared.global [%0], [%1], 16;" :: "r"(s), "l"(g));
}
#define CP_COMMIT() asm volatile("cp.async.commit_group;" ::: "memory")

__device__ __forceinline__ void ldmat4(uint32_t (&r)[4], uint32_t addr) {
    asm volatile("ldmatrix.sync.aligned.m8n8.x4.shared.b16 {%0,%1,%2,%3}, [%4];"
                 : "=r"(r[0]), "=r"(r[1]), "=r"(r[2]), "=r"(r[3]) : "r"(addr));
}
__device__ __forceinline__ void mma16816(float (&d)[4], const uint32_t (&a)[4],
                                         const uint32_t b0, const uint32_t b1) {
    asm volatile(
        "mma.sync.aligned.m16n8k16.row.col.f32.bf16.bf16.f32 "
        "{%0,%1,%2,%3},{%4,%5,%6,%7},{%8,%9},{%0,%1,%2,%3};"
        : "+f"(d[0]), "+f"(d[1]), "+f"(d[2]), "+f"(d[3])
        : "r"(a[0]), "r"(a[1]), "r"(a[2]), "r"(a[3]), "r"(b0), "r"(b1));
}

// split helpers: x = hi + lo (bf16 each)
__device__ __forceinline__ void split2(float x, __nv_bfloat16& hi, __nv_bfloat16& lo) {
    hi = __float2bfloat16(x);
    lo = __float2bfloat16(x - __bfloat162float(hi));
}

// ---------------- mma.sync GEMM ----------------
// C = alpha * A2[M,3K] (x) B2[N,3K]^T  over augmented K (chunk-interleaved per 64)
// EPI: 0=f32*alpha  1=f32+bias  2=f32+bias+res  3=splitA  4=splitA+bias
//      5=splitA+bias+relu  6=splitB+bias
#define E_SC 0
#define E_FB 1
#define E_FBR 2
#define E_SA 3
#define E_SAB 4
#define E_SABR 5
#define E_SBB 6

#define BKA 32          // augmented-K per stage (bf16)
#define SSTR 40         // padded smem row stride in bf16 elems (80 bytes)

template <int EPI, bool CSKIP, bool CKLIM>
__global__ __launch_bounds__(256)
void tgemm(const __nv_bfloat16* __restrict__ A2, const __nv_bfloat16* __restrict__ B2,
           const float* __restrict__ bias, const float* __restrict__ res,
           void* __restrict__ Cp, int Ksrc, int Nsrc, float alpha,
           long aRows, long bRows, long cRows)
{
    const int brow = blockIdx.y * 128;
    const int bcol = blockIdx.x * 128;
    if (CSKIP && bcol > brow + 127) return;
    const int z = blockIdx.z;

    __shared__ __align__(16) __nv_bfloat16 As[2][128][SSTR];
    __shared__ __align__(16) __nv_bfloat16 Bs[2][128][SSTR];

    const int tid = threadIdx.x;
    const int lane = tid & 31;
    const int w = tid >> 5;
    const int wm = (w & 3) * 32;    // warp m offset within tile
    const int wn = (w >> 2) * 64;   // warp n offset within tile

    const long lda = 3L * Ksrc;
    const __nv_bfloat16* Arow = A2 + ((long)z * aRows + brow) * lda;
    const __nv_bfloat16* Brow = B2 + ((long)z * bRows + bcol) * lda;

    const int nk = (CKLIM ? 3 * min(Ksrc, brow + 128) : 3 * Ksrc) / BKA;

    float acc[2][8][4];
#pragma unroll
    for (int i = 0; i < 2; ++i)
#pragma unroll
        for (int j = 0; j < 8; ++j)
#pragma unroll
            for (int u = 0; u < 4; ++u) acc[i][j][u] = 0.f;

    // cp.async tile loader: 512 16B chunks per operand, 256 threads -> 2 iters
    auto load_tile = [&](int t, int buf) {
        const int k0 = t * BKA;
#pragma unroll
        for (int it = 0; it < 2; ++it) {
            const int idx = tid + it * 256;
            const int row = idx >> 2;
            const int ch  = idx & 3;
            cp16(s2u(&As[buf][row][ch * 8]), Arow + (long)row * lda + k0 + ch * 8);
            cp16(s2u(&Bs[buf][row][ch * 8]), Brow + (long)row * lda + k0 + ch * 8);
        }
    };

    // ldmatrix lane offsets
    const int a_moff = (lane & 7) + ((lane >> 3) & 1) * 8;
    const int a_koff = (lane >> 4) * 8;
    const int b_noff = (lane & 7) + (lane >> 4) * 8;
    const int b_koff = ((lane >> 3) & 1) * 8;

    load_tile(0, 0);
    CP_COMMIT();

    for (int t = 0; t < nk; ++t) {
        if (t + 1 < nk) {
            load_tile(t + 1, (t + 1) & 1);
            CP_COMMIT();
            asm volatile("cp.async.wait_group 1;" ::: "memory");
        } else {
            asm volatile("cp.async.wait_group 0;" ::: "memory");
        }
        __syncthreads();
        const int buf = t & 1;
#pragma unroll
        for (int ks = 0; ks < 2; ++ks) {
            uint32_t a[2][4];
#pragma unroll
            for (int mi = 0; mi < 2; ++mi)
                ldmat4(a[mi], s2u(&As[buf][wm + mi * 16 + a_moff][ks * 16 + a_koff]));
            uint32_t b[8][2];
#pragma unroll
            for (int np = 0; np < 4; ++np) {
                uint32_t bb[4];
                ldmat4(bb, s2u(&Bs[buf][wn + np * 16 + b_noff][ks * 16 + b_koff]));
                b[np * 2][0] = bb[0]; b[np * 2][1] = bb[1];
                b[np * 2 + 1][0] = bb[2]; b[np * 2 + 1][1] = bb[3];
            }
#pragma unroll
            for (int mi = 0; mi < 2; ++mi)
#pragma unroll
                for (int nj = 0; nj < 8; ++nj)
                    mma16816(acc[mi][nj], a[mi], b[nj][0], b[nj][1]);
        }
        __syncthreads();
    }

    // ---------------- epilogue ----------------
#pragma unroll
    for (int mi = 0; mi < 2; ++mi) {
#pragma unroll
        for (int half = 0; half < 2; ++half) {
            const int r = brow + wm + mi * 16 + (lane >> 2) + half * 8;
#pragma unroll
            for (int nj = 0; nj < 8; ++nj) {
                const int c = bcol + wn + nj * 8 + 2 * (lane & 3);
                float v0 = acc[mi][nj][half * 2 + 0] * alpha;
                float v1 = acc[mi][nj][half * 2 + 1] * alpha;

                if (EPI == E_SC || EPI == E_FB || EPI == E_FBR) {
                    if (EPI == E_FB || EPI == E_FBR) { v0 += bias[c]; v1 += bias[c + 1]; }
                    if (EPI == E_FBR) {
                        const float2 rv = *reinterpret_cast<const float2*>(
                            res + (long)r * Nsrc + c);
                        v0 += rv.x; v1 += rv.y;
                    }
                    float2 o; o.x = v0; o.y = v1;
                    *reinterpret_cast<float2*>(
                        (float*)Cp + ((long)z * cRows + r) * (long)Nsrc + c) = o;
                } else {
                    if (EPI == E_SAB || EPI == E_SABR || EPI == E_SBB) {
                        v0 += bias[c]; v1 += bias[c + 1];
                    }
                    if (EPI == E_SABR) { v0 = fmaxf(v0, 0.f); v1 = fmaxf(v1, 0.f); }
                    __nv_bfloat16 h0, l0, h1, l1;
                    split2(v0, h0, l0);
                    split2(v1, h1, l1);
                    __nv_bfloat162 hh; hh.x = h0; hh.y = h1;
                    __nv_bfloat162 ll; ll.x = l0; ll.y = l1;
                    __nv_bfloat16* Cb = (__nv_bfloat16*)Cp;
                    const long base = ((long)z * cRows + r) * (3L * Nsrc)
                                    + (long)(c >> 6) * 192 + (c & 63);
                    *reinterpret_cast<__nv_bfloat162*>(Cb + base) = hh;
                    if (EPI == E_SBB) {  // B-pattern [hi, lo, hi]
                        *reinterpret_cast<__nv_bfloat162*>(Cb + base + 64)  = ll;
                        *reinterpret_cast<__nv_bfloat162*>(Cb + base + 128) = hh;
                    } else {             // A-pattern [hi, hi, lo]
                        *reinterpret_cast<__nv_bfloat162*>(Cb + base + 64)  = hh;
                        *reinterpret_cast<__nv_bfloat162*>(Cb + base + 128) = ll;
                    }
                }
            }
        }
    }
}

// ---------------- LayerNorm -> split-A bf16 output ----------------
__global__ __launch_bounds__(256)
void layernorm_split(const float* __restrict__ x, const float* __restrict__ gamma,
                     const float* __restrict__ beta, __nv_bfloat16* __restrict__ y2)
{
    const long rowi = blockIdx.x;
    const float* xr = x + rowi * Dc;
    __nv_bfloat16* yr = y2 + rowi * (long)K3D;
    __shared__ float red[256];
    const int tid = threadIdx.x;

    float s = 0.f;
    for (int i = tid; i < Dc; i += 256) s += xr[i];
    red[tid] = s; __syncthreads();
    for (int st = 128; st > 0; st >>= 1) {
        if (tid < st) red[tid] += red[tid + st];
        __syncthreads();
    }
    const float mean = red[0] / (float)Dc;
    __syncthreads();

    float v = 0.f;
    for (int i = tid; i < Dc; i += 256) {
        const float d = xr[i] - mean;
        v += d * d;
    }
    red[tid] = v; __syncthreads();
    for (int st = 128; st > 0; st >>= 1) {
        if (tid < st) red[tid] += red[tid + st];
        __syncthreads();
    }
    const float var = red[0] / (float)(Dc - 1);
    const float inv = 1.f / (sqrtf(var) + 1e-6f);

    for (int i = tid; i < Dc; i += 256) {
        const float yv = gamma[i] * (xr[i] - mean) * inv + beta[i];
        __nv_bfloat16 hi, lo;
        split2(yv, hi, lo);
        const long base = (long)(i >> 6) * 192 + (i & 63);
        yr[base] = hi; yr[base + 64] = hi; yr[base + 128] = lo;
    }
}

// ---------------- causal softmax -> split-A bf16 (+zero pad to block) -------
__global__ __launch_bounds__(256)
void softmax_split(const float* __restrict__ sc, __nv_bfloat16* __restrict__ a2)
{
    const int m = blockIdx.x;
    const int b = blockIdx.y;
    const float* row = sc + ((long)b * Sc + m) * (long)Sc;
    __nv_bfloat16* orow = a2 + ((long)b * Sc + m) * (long)K3S;
    const int n = m + 1;
    __shared__ float red[256];
    const int tid = threadIdx.x;

    float lmax = -1e30f;
    for (int i = tid; i < n; i += 256) lmax = fmaxf(lmax, row[i]);
    red[tid] = lmax; __syncthreads();
    for (int st = 128; st > 0; st >>= 1) {
        if (tid < st) red[tid] = fmaxf(red[tid], red[tid + st]);
        __syncthreads();
    }
    const float gmax = red[0];
    __syncthreads();

    float lsum = 0.f;
    for (int i = tid; i < n; i += 256) lsum += __expf(row[i] - gmax);
    red[tid] = lsum; __syncthreads();
    for (int st = 128; st > 0; st >>= 1) {
        if (tid < st) red[tid] += red[tid + st];
        __syncthreads();
    }
    const float inv = 1.f / red[0];

    for (int i = tid; i < n; i += 256) {
        const float p = __expf(row[i] - gmax) * inv;
        __nv_bfloat16 hi, lo;
        split2(p, hi, lo);
        const long base = (long)(i >> 6) * 192 + (i & 63);
        orow[base] = hi; orow[base + 64] = hi; orow[base + 128] = lo;
    }
    // zero-fill (m, m|127] so the AV block-K-limit reads zeros
    const int lim = (m | 127);
    for (int i = n + tid; i <= lim; i += 256) {
        const long base = (long)(i >> 6) * 192 + (i & 63);
        const __nv_bfloat16 zz = __float2bfloat16(0.f);
        orow[base] = zz; orow[base + 64] = zz; orow[base + 128] = zz;
    }
}

// ---------------- transpose + split (B-pattern) ----------------
// src: fp32 [R, C] (row-major) per batch; dst: bf16 [C, 3R] chunk-interleaved.
__global__ __launch_bounds__(256)
void transsplit(const float* __restrict__ src, __nv_bfloat16* __restrict__ dst,
                int R, int C, long srcBatch, long dstBatch)
{
    const int zb = blockIdx.z;
    src += (long)zb * srcBatch;
    dst += (long)zb * dstBatch;
    __shared__ float t[32][33];
    const int c0 = blockIdx.x * 32;
    const int r0 = blockIdx.y * 32;
    const int tx = threadIdx.x, ty = threadIdx.y;  // 32 x 8

    #pragma unroll
    for (int i = 0; i < 4; ++i)
        t[ty + 8 * i][tx] = src[(long)(r0 + ty + 8 * i) * C + c0 + tx];
    __syncthreads();

    #pragma unroll
    for (int i = 0; i < 4; ++i) {
        const int c = c0 + ty + 8 * i;   // dst row
        const int k = r0 + tx;           // source-K index
        const float val = t[tx][ty + 8 * i];
        __nv_bfloat16 hi, lo;
        split2(val, hi, lo);
        const long base = (long)c * (3L * R) + (long)(k >> 6) * 192 + (k & 63);
        dst[base] = hi; dst[base + 64] = lo; dst[base + 128] = hi;
    }
}

// ---------------------------------------------------------------------------
extern "C" void kernel_launch(void* const* d_in, const int* in_sizes, int n_in,
                              void* d_out, int out_size)
{
    const float* x   = (const float*)d_in[0];
    const float* wq  = (const float*)d_in[1];
    const float* bq  = (const float*)d_in[2];
    const float* wk  = (const float*)d_in[3];
    const float* bk  = (const float*)d_in[4];
    const float* wv  = (const float*)d_in[5];
    const float* bv  = (const float*)d_in[6];
    const float* wo  = (const float*)d_in[7];
    const float* bo  = (const float*)d_in[8];
    const float* w1  = (const float*)d_in[9];
    const float* b1  = (const float*)d_in[10];
    const float* w2  = (const float*)d_in[11];
    const float* b2  = (const float*)d_in[12];
    const float* g1  = (const float*)d_in[13];
    const float* be1 = (const float*)d_in[14];
    const float* g2  = (const float*)d_in[15];
    const float* be2 = (const float*)d_in[16];
    float* out = (float*)d_out;

    __nv_bfloat16 *xn2, *q2, *k2, *vt2, *a2, *ao2, *m2, *f2, *wt2;
    float *v, *s, *h;
    cudaGetSymbolAddress((void**)&xn2, g_xn2);
    cudaGetSymbolAddress((void**)&q2,  g_q2);
    cudaGetSymbolAddress((void**)&k2,  g_k2);
    cudaGetSymbolAddress((void**)&v,   g_v);
    cudaGetSymbolAddress((void**)&vt2, g_vt2);
    cudaGetSymbolAddress((void**)&s,   g_s);
    cudaGetSymbolAddress((void**)&a2,  g_a2);
    cudaGetSymbolAddress((void**)&ao2, g_ao2);
    cudaGetSymbolAddress((void**)&h,   g_h);
    cudaGetSymbolAddress((void**)&m2,  g_m2);
    cudaGetSymbolAddress((void**)&f2,  g_f2);
    cudaGetSymbolAddress((void**)&wt2, g_wt2);

    __nv_bfloat16* wqt = wt2 + 0L * Dc * K3D;
    __nv_bfloat16* wkt = wt2 + 1L * Dc * K3D;
    __nv_bfloat16* wvt = wt2 + 2L * Dc * K3D;
    __nv_bfloat16* wot = wt2 + 3L * Dc * K3D;
    __nv_bfloat16* w1t = wt2 + 4L * Dc * K3D;
    __nv_bfloat16* w2t = wt2 + 5L * Dc * K3D;

    const float inv_sqrt_s = 1.0f / sqrtf((float)Sc);
    const dim3 tb(32, 8);
    const dim3 gW(Dc / 32, Dc / 32, 1);
    const dim3 gV(Dc / 32, Sc / 32, Bc);
    const dim3 gProj(Dc / 128, Mc / 128, 1);     // 8 x 64
    const dim3 gScore(Sc / 128, Sc / 128, Bc);   // 16 x 16 x 4
    const dim3 gAV(Dc / 128, Sc / 128, Bc);      // 8 x 16 x 4

    // weight transpose+split (B-pattern)
    transsplit<<<gW, tb>>>(wq, wqt, Dc, Dc, 0, 0);
    transsplit<<<gW, tb>>>(wk, wkt, Dc, Dc, 0, 0);
    transsplit<<<gW, tb>>>(wv, wvt, Dc, Dc, 0, 0);
    transsplit<<<gW, tb>>>(wo, wot, Dc, Dc, 0, 0);
    transsplit<<<gW, tb>>>(w1, w1t, Dc, Dc, 0, 0);
    transsplit<<<gW, tb>>>(w2, w2t, Dc, Dc, 0, 0);

    // 1) LN1 -> xn2 (split-A)
    layernorm_split<<<Mc, 256>>>(x, g1, be1, xn2);

    // 2) projections
    tgemm<E_SAB, false, false><<<gProj, 256>>>(
        xn2, wqt, bq, nullptr, q2, Dc, Dc, 1.f, 0, 0, 0);
    tgemm<E_SBB, false, false><<<gProj, 256>>>(
        xn2, wkt, bk, nullptr, k2, Dc, Dc, 1.f, 0, 0, 0);
    tgemm<E_FB, false, false><<<gProj, 256>>>(
        xn2, wvt, bv, nullptr, v, Dc, Dc, 1.f, 0, 0, 0);

    // 3) v -> vt2 (transpose + split-B), per batch
    transsplit<<<gV, tb>>>(v, vt2, Sc, Dc, (long)Sc * Dc, (long)Dc * K3S);

    // 4) scores = (q k^T)/sqrt(S), causal tiles skipped
    tgemm<E_SC, true, false><<<gScore, 256>>>(
        q2, k2, nullptr, nullptr, s, Dc, Sc, inv_sqrt_s, Sc, Sc, Sc);

    // 5) softmax -> a2 (split-A + zero pad)
    softmax_split<<<dim3(Sc, Bc), 256>>>(s, a2);

    // 6) attn @ V with block-K limit -> ao2 (split-A)
    tgemm<E_SA, false, true><<<gAV, 256>>>(
        a2, vt2, nullptr, nullptr, ao2, Sc, Dc, 1.f, Sc, Dc, Sc);

    // 7) h = ao @ wo + bo + x
    tgemm<E_FBR, false, false><<<gProj, 256>>>(
        ao2, wot, bo, x, h, Dc, Dc, 1.f, 0, 0, 0);

    // 8) LN2 -> m2 (split-A)
    layernorm_split<<<Mc, 256>>>(h, g2, be2, m2);

    // 9) f2 = relu(m @ w1 + b1) (split-A)
    tgemm<E_SABR, false, false><<<gProj, 256>>>(
        m2, w1t, b1, nullptr, f2, Dc, Dc, 1.f, 0, 0, 0);

    // 10) out = f @ w2 + b2 + h
    tgemm<E_FBR, false, false><<<gProj, 256>>>(
        f2, w2t, b2, h, out, Dc, Dc, 1.f, 0, 0, 0);
}

// round 4
// speedup vs baseline: 2.8355x; 1.4426x over previous
#include <cuda_runtime.h>
#include <cuda_bf16.h>
#include <math.h>
#include <stdint.h>

// ---------------- problem shape ----------------
#define Bc 4
#define Sc 2048
#define Dc 1024
#define Mc (Bc * Sc)
#define K3D (3 * Dc)   // 3072 augmented-K for D-sized contractions
#define K3S (3 * Sc)   // 6144 augmented-K for S-sized contractions

// ---------------- scratch (device globals; no allocation allowed) ----------
__device__ __align__(256) __nv_bfloat16 g_xn2[(size_t)Mc * K3D];
__device__ __align__(256) __nv_bfloat16 g_q2 [(size_t)Mc * K3D];
__device__ __align__(256) __nv_bfloat16 g_k2 [(size_t)Mc * K3D];
__device__ __align__(256) float         g_v  [(size_t)Mc * Dc];
__device__ __align__(256) __nv_bfloat16 g_vt2[(size_t)Bc * Dc * K3S];
__device__ __align__(256) float         g_s  [(size_t)Bc * Sc * Sc];
__device__ __align__(256) __nv_bfloat16 g_a2 [(size_t)Mc * K3S];
__device__ __align__(256) __nv_bfloat16 g_ao2[(size_t)Mc * K3D];
__device__ __align__(256) float         g_h  [(size_t)Mc * Dc];
__device__ __align__(256) __nv_bfloat16 g_m2 [(size_t)Mc * K3D];
__device__ __align__(256) __nv_bfloat16 g_f2 [(size_t)Mc * K3D];
__device__ __align__(256) __nv_bfloat16 g_wt2[6][(size_t)Dc * K3D];

// ---------------- PTX helpers ----------------
__device__ __forceinline__ uint32_t s2u(const void* p) {
    uint32_t a;
    asm("{ .reg .u64 t; cvta.to.shared.u64 t, %1; cvt.u32.u64 %0, t; }"
        : "=r"(a) : "l"(p));
    return a;
}
__device__ __forceinline__ void cp16(uint32_t s, const void* g) {
    asm volatile("cp.async.cg.shared.global [%0], [%1], 16;" :: "r"(s), "l"(g));
}
#define CP_COMMIT() asm volatile("cp.async.commit_group;" ::: "memory")
#define CP_WAIT1()  asm volatile("cp.async.wait_group 1;" ::: "memory")

__device__ __forceinline__ void ldmat4(uint32_t (&r)[4], uint32_t addr) {
    asm volatile("ldmatrix.sync.aligned.m8n8.x4.shared.b16 {%0,%1,%2,%3}, [%4];"
                 : "=r"(r[0]), "=r"(r[1]), "=r"(r[2]), "=r"(r[3]) : "r"(addr));
}
__device__ __forceinline__ void mma16816(float (&d)[4], const uint32_t (&a)[4],
                                         const uint32_t b0, const uint32_t b1) {
    asm volatile(
        "mma.sync.aligned.m16n8k16.row.col.f32.bf16.bf16.f32 "
        "{%0,%1,%2,%3},{%4,%5,%6,%7},{%8,%9},{%0,%1,%2,%3};"
        : "+f"(d[0]), "+f"(d[1]), "+f"(d[2]), "+f"(d[3])
        : "r"(a[0]), "r"(a[1]), "r"(a[2]), "r"(a[3]), "r"(b0), "r"(b1));
}

// split helpers: x = hi + lo (bf16 each)
__device__ __forceinline__ void split2(float x, __nv_bfloat16& hi, __nv_bfloat16& lo) {
    hi = __float2bfloat16(x);
    lo = __float2bfloat16(x - __bfloat162float(hi));
}

// ---------------- mma.sync GEMM (64x64 warp tile, 3-stage) ----------------
// C = alpha * A2[M,3K] (x) B2[N,3K]^T  over augmented K (chunk-interleaved per 64)
#define E_SC 0
#define E_FB 1
#define E_FBR 2
#define E_SA 3
#define E_SAB 4
#define E_SABR 5
#define E_SBB 6

#define BKA 32          // augmented-K per stage (bf16)
#define SSTR 40         // padded smem row stride in bf16 (80 bytes)
#define STG_B (128 * SSTR * 2)       // one operand tile = 10240 B
#define STAGE_B (2 * STG_B)          // A+B per stage   = 20480 B
#define NSTG 3
#define SMEM_SZ (NSTG * STAGE_B)     // 61440 B

template <int EPI, bool CSKIP, bool CKLIM>
__global__ __launch_bounds__(128, 2)
void tgemm(const __nv_bfloat16* __restrict__ A2, const __nv_bfloat16* __restrict__ B2,
           const float* __restrict__ bias, const float* __restrict__ res,
           void* __restrict__ Cp, int Ksrc, int Nsrc, float alpha,
           long aRows, long bRows, long cRows)
{
    const int brow = blockIdx.y * 128;
    const int bcol = blockIdx.x * 128;
    if (CSKIP && bcol > brow + 127) return;
    const int z = blockIdx.z;

    extern __shared__ __align__(16) char smem[];
    const uint32_t sb = s2u(smem);

    const int tid = threadIdx.x;
    const int lane = tid & 31;
    const int w = tid >> 5;
    const int wm = (w & 1) * 64;
    const int wn = (w >> 1) * 64;

    const long lda = 3L * Ksrc;
    const __nv_bfloat16* Arow = A2 + ((long)z * aRows + brow) * lda;
    const __nv_bfloat16* Brow = B2 + ((long)z * bRows + bcol) * lda;

    const int nk = (CKLIM ? 3 * min(Ksrc, brow + 128) : 3 * Ksrc) / BKA;

    float acc[4][8][4];
#pragma unroll
    for (int i = 0; i < 4; ++i)
#pragma unroll
        for (int j = 0; j < 8; ++j)
#pragma unroll
            for (int u = 0; u < 4; ++u) acc[i][j][u] = 0.f;

    // loader: per stage, A and B are 128 rows x 32 bf16 (4 x 16B chunks/row)
    auto load_tile = [&](int t) {
        const int k0 = t * BKA;
        const uint32_t base = sb + (t % NSTG) * STAGE_B;
#pragma unroll
        for (int it = 0; it < 4; ++it) {
            const int idx = tid + it * 128;
            const int row = idx >> 2;
            const int ch  = idx & 3;
            const uint32_t off = row * (SSTR * 2) + ch * 16;
            cp16(base + off,         Arow + (long)row * lda + k0 + ch * 8);
            cp16(base + STG_B + off, Brow + (long)row * lda + k0 + ch * 8);
        }
    };

    // ldmatrix lane offsets
    const int a_moff = lane & 15;
    const int a_koff = (lane >> 4) * 8;
    const int b_noff = (lane & 7) + (lane >> 4) * 8;
    const int b_koff = ((lane >> 3) & 1) * 8;

    load_tile(0); CP_COMMIT();
    load_tile(1); CP_COMMIT();
    CP_WAIT1();
    __syncthreads();

    for (int t = 0; t < nk; ++t) {
        if (t + 2 < nk) load_tile(t + 2);
        CP_COMMIT();                        // one group per iter (maybe empty)

        const uint32_t abase = sb + (t % NSTG) * STAGE_B;
        const uint32_t bbase = abase + STG_B;
#pragma unroll
        for (int ks = 0; ks < 2; ++ks) {
            uint32_t a[4][4];
#pragma unroll
            for (int mi = 0; mi < 4; ++mi)
                ldmat4(a[mi], abase + (uint32_t)((wm + mi * 16 + a_moff) * (SSTR * 2)
                                                 + (ks * 16 + a_koff) * 2));
            uint32_t b[8][2];
#pragma unroll
            for (int np = 0; np < 4; ++np) {
                uint32_t bb[4];
                ldmat4(bb, bbase + (uint32_t)((wn + np * 16 + b_noff) * (SSTR * 2)
                                              + (ks * 16 + b_koff) * 2));
                b[np * 2][0] = bb[0]; b[np * 2][1] = bb[1];
                b[np * 2 + 1][0] = bb[2]; b[np * 2 + 1][1] = bb[3];
            }
#pragma unroll
            for (int mi = 0; mi < 4; ++mi)
#pragma unroll
                for (int nj = 0; nj < 8; ++nj)
                    mma16816(acc[mi][nj], a[mi], b[nj][0], b[nj][1]);
        }
        CP_WAIT1();        // stage t+1 resident
        __syncthreads();   // stage (t+2)%3 free for next iter's loads
    }

    // ---------------- epilogue ----------------
#pragma unroll
    for (int mi = 0; mi < 4; ++mi) {
#pragma unroll
        for (int half = 0; half < 2; ++half) {
            const int r = brow + wm + mi * 16 + (lane >> 2) + half * 8;
#pragma unroll
            for (int nj = 0; nj < 8; ++nj) {
                const int c = bcol + wn + nj * 8 + 2 * (lane & 3);
                float v0 = acc[mi][nj][half * 2 + 0] * alpha;
                float v1 = acc[mi][nj][half * 2 + 1] * alpha;

                if (EPI == E_SC || EPI == E_FB || EPI == E_FBR) {
                    if (EPI == E_FB || EPI == E_FBR) { v0 += bias[c]; v1 += bias[c + 1]; }
                    if (EPI == E_FBR) {
                        const float2 rv = *reinterpret_cast<const float2*>(
                            res + (long)r * Nsrc + c);
                        v0 += rv.x; v1 += rv.y;
                    }
                    float2 o; o.x = v0; o.y = v1;
                    *reinterpret_cast<float2*>(
                        (float*)Cp + ((long)z * cRows + r) * (long)Nsrc + c) = o;
                } else {
                    if (EPI == E_SAB || EPI == E_SABR || EPI == E_SBB) {
                        v0 += bias[c]; v1 += bias[c + 1];
                    }
                    if (EPI == E_SABR) { v0 = fmaxf(v0, 0.f); v1 = fmaxf(v1, 0.f); }
                    __nv_bfloat16 h0, l0, h1, l1;
                    split2(v0, h0, l0);
                    split2(v1, h1, l1);
                    __nv_bfloat162 hh; hh.x = h0; hh.y = h1;
                    __nv_bfloat162 ll; ll.x = l0; ll.y = l1;
                    __nv_bfloat16* Cb = (__nv_bfloat16*)Cp;
                    const long base = ((long)z * cRows + r) * (3L * Nsrc)
                                    + (long)(c >> 6) * 192 + (c & 63);
                    *reinterpret_cast<__nv_bfloat162*>(Cb + base) = hh;
                    if (EPI == E_SBB) {  // B-pattern [hi, lo, hi]
                        *reinterpret_cast<__nv_bfloat162*>(Cb + base + 64)  = ll;
                        *reinterpret_cast<__nv_bfloat162*>(Cb + base + 128) = hh;
                    } else {             // A-pattern [hi, hi, lo]
                        *reinterpret_cast<__nv_bfloat162*>(Cb + base + 64)  = hh;
                        *reinterpret_cast<__nv_bfloat162*>(Cb + base + 128) = ll;
                    }
                }
            }
        }
    }
}

// ---------------- LayerNorm -> split-A bf16 output ----------------
__global__ __launch_bounds__(256)
void layernorm_split(const float* __restrict__ x, const float* __restrict__ gamma,
                     const float* __restrict__ beta, __nv_bfloat16* __restrict__ y2)
{
    const long rowi = blockIdx.x;
    const float* xr = x + rowi * Dc;
    __nv_bfloat16* yr = y2 + rowi * (long)K3D;
    __shared__ float red[256];
    const int tid = threadIdx.x;

    float s = 0.f;
    for (int i = tid; i < Dc; i += 256) s += xr[i];
    red[tid] = s; __syncthreads();
    for (int st = 128; st > 0; st >>= 1) {
        if (tid < st) red[tid] += red[tid + st];
        __syncthreads();
    }
    const float mean = red[0] / (float)Dc;
    __syncthreads();

    float v = 0.f;
    for (int i = tid; i < Dc; i += 256) {
        const float d = xr[i] - mean;
        v += d * d;
    }
    red[tid] = v; __syncthreads();
    for (int st = 128; st > 0; st >>= 1) {
        if (tid < st) red[tid] += red[tid + st];
        __syncthreads();
    }
    const float var = red[0] / (float)(Dc - 1);
    const float inv = 1.f / (sqrtf(var) + 1e-6f);

    for (int i = tid; i < Dc; i += 256) {
        const float yv = gamma[i] * (xr[i] - mean) * inv + beta[i];
        __nv_bfloat16 hi, lo;
        split2(yv, hi, lo);
        const long base = (long)(i >> 6) * 192 + (i & 63);
        yr[base] = hi; yr[base + 64] = hi; yr[base + 128] = lo;
    }
}

// ---------------- causal softmax -> split-A bf16 (+zero pad to block) -------
__global__ __launch_bounds__(256)
void softmax_split(const float* __restrict__ sc, __nv_bfloat16* __restrict__ a2)
{
    const int m = blockIdx.x;
    const int b = blockIdx.y;
    const float* row = sc + ((long)b * Sc + m) * (long)Sc;
    __nv_bfloat16* orow = a2 + ((long)b * Sc + m) * (long)K3S;
    const int n = m + 1;
    __shared__ float red[256];
    const int tid = threadIdx.x;

    float lmax = -1e30f;
    for (int i = tid; i < n; i += 256) lmax = fmaxf(lmax, row[i]);
    red[tid] = lmax; __syncthreads();
    for (int st = 128; st > 0; st >>= 1) {
        if (tid < st) red[tid] = fmaxf(red[tid], red[tid + st]);
        __syncthreads();
    }
    const float gmax = red[0];
    __syncthreads();

    float lsum = 0.f;
    for (int i = tid; i < n; i += 256) lsum += __expf(row[i] - gmax);
    red[tid] = lsum; __syncthreads();
    for (int st = 128; st > 0; st >>= 1) {
        if (tid < st) red[tid] += red[tid + st];
        __syncthreads();
    }
    const float inv = 1.f / red[0];

    for (int i = tid; i < n; i += 256) {
        const float p = __expf(row[i] - gmax) * inv;
        __nv_bfloat16 hi, lo;
        split2(p, hi, lo);
        const long base = (long)(i >> 6) * 192 + (i & 63);
        orow[base] = hi; orow[base + 64] = hi; orow[base + 128] = lo;
    }
    // zero-fill (m, m|127] so the AV block-K-limit reads zeros
    const int lim = (m | 127);
    for (int i = n + tid; i <= lim; i += 256) {
        const long base = (long)(i >> 6) * 192 + (i & 63);
        const __nv_bfloat16 zz = __float2bfloat16(0.f);
        orow[base] = zz; orow[base + 64] = zz; orow[base + 128] = zz;
    }
}

// ---------------- transpose + split (B-pattern) ----------------
__global__ __launch_bounds__(256)
void transsplit(const float* __restrict__ src, __nv_bfloat16* __restrict__ dst,
                int R, int C, long srcBatch, long dstBatch)
{
    const int zb = blockIdx.z;
    src += (long)zb * srcBatch;
    dst += (long)zb * dstBatch;
    __shared__ float t[32][33];
    const int c0 = blockIdx.x * 32;
    const int r0 = blockIdx.y * 32;
    const int tx = threadIdx.x, ty = threadIdx.y;  // 32 x 8

    #pragma unroll
    for (int i = 0; i < 4; ++i)
        t[ty + 8 * i][tx] = src[(long)(r0 + ty + 8 * i) * C + c0 + tx];
    __syncthreads();

    #pragma unroll
    for (int i = 0; i < 4; ++i) {
        const int c = c0 + ty + 8 * i;   // dst row
        const int k = r0 + tx;           // source-K index
        const float val = t[tx][ty + 8 * i];
        __nv_bfloat16 hi, lo;
        split2(val, hi, lo);
        const long base = (long)c * (3L * R) + (long)(k >> 6) * 192 + (k & 63);
        dst[base] = hi; dst[base + 64] = lo; dst[base + 128] = hi;
    }
}

// ---------------------------------------------------------------------------
extern "C" void kernel_launch(void* const* d_in, const int* in_sizes, int n_in,
                              void* d_out, int out_size)
{
    const float* x   = (const float*)d_in[0];
    const float* wq  = (const float*)d_in[1];
    const float* bq  = (const float*)d_in[2];
    const float* wk  = (const float*)d_in[3];
    const float* bk  = (const float*)d_in[4];
    const float* wv  = (const float*)d_in[5];
    const float* bv  = (const float*)d_in[6];
    const float* wo  = (const float*)d_in[7];
    const float* bo  = (const float*)d_in[8];
    const float* w1  = (const float*)d_in[9];
    const float* b1  = (const float*)d_in[10];
    const float* w2  = (const float*)d_in[11];
    const float* b2  = (const float*)d_in[12];
    const float* g1  = (const float*)d_in[13];
    const float* be1 = (const float*)d_in[14];
    const float* g2  = (const float*)d_in[15];
    const float* be2 = (const float*)d_in[16];
    float* out = (float*)d_out;

    __nv_bfloat16 *xn2, *q2, *k2, *vt2, *a2, *ao2, *m2, *f2, *wt2;
    float *v, *s, *h;
    cudaGetSymbolAddress((void**)&xn2, g_xn2);
    cudaGetSymbolAddress((void**)&q2,  g_q2);
    cudaGetSymbolAddress((void**)&k2,  g_k2);
    cudaGetSymbolAddress((void**)&v,   g_v);
    cudaGetSymbolAddress((void**)&vt2, g_vt2);
    cudaGetSymbolAddress((void**)&s,   g_s);
    cudaGetSymbolAddress((void**)&a2,  g_a2);
    cudaGetSymbolAddress((void**)&ao2, g_ao2);
    cudaGetSymbolAddress((void**)&h,   g_h);
    cudaGetSymbolAddress((void**)&m2,  g_m2);
    cudaGetSymbolAddress((void**)&f2,  g_f2);
    cudaGetSymbolAddress((void**)&wt2, g_wt2);

    __nv_bfloat16* wqt = wt2 + 0L * Dc * K3D;
    __nv_bfloat16* wkt = wt2 + 1L * Dc * K3D;
    __nv_bfloat16* wvt = wt2 + 2L * Dc * K3D;
    __nv_bfloat16* wot = wt2 + 3L * Dc * K3D;
    __nv_bfloat16* w1t = wt2 + 4L * Dc * K3D;
    __nv_bfloat16* w2t = wt2 + 5L * Dc * K3D;

    cudaFuncSetAttribute((const void*)tgemm<E_SAB, false, false>, cudaFuncAttributeMaxDynamicSharedMemorySize, SMEM_SZ);
    cudaFuncSetAttribute((const void*)tgemm<E_SBB, false, false>, cudaFuncAttributeMaxDynamicSharedMemorySize, SMEM_SZ);
    cudaFuncSetAttribute((const void*)tgemm<E_FB,  false, false>, cudaFuncAttributeMaxDynamicSharedMemorySize, SMEM_SZ);
    cudaFuncSetAttribute((const void*)tgemm<E_SC,  true,  false>, cudaFuncAttributeMaxDynamicSharedMemorySize, SMEM_SZ);
    cudaFuncSetAttribute((const void*)tgemm<E_SA,  false, true >, cudaFuncAttributeMaxDynamicSharedMemorySize, SMEM_SZ);
    cudaFuncSetAttribute((const void*)tgemm<E_FBR, false, false>, cudaFuncAttributeMaxDynamicSharedMemorySize, SMEM_SZ);
    cudaFuncSetAttribute((const void*)tgemm<E_SABR,false, false>, cudaFuncAttributeMaxDynamicSharedMemorySize, SMEM_SZ);

    const float inv_sqrt_s = 1.0f / sqrtf((float)Sc);
    const dim3 tb(32, 8);
    const dim3 gW(Dc / 32, Dc / 32, 1);
    const dim3 gV(Dc / 32, Sc / 32, Bc);
    const dim3 gProj(Dc / 128, Mc / 128, 1);     // 8 x 64
    const dim3 gScore(Sc / 128, Sc / 128, Bc);   // 16 x 16 x 4
    const dim3 gAV(Dc / 128, Sc / 128, Bc);      // 8 x 16 x 4

    // weight transpose+split (B-pattern)
    transsplit<<<gW, tb>>>(wq, wqt, Dc, Dc, 0, 0);
    transsplit<<<gW, tb>>>(wk, wkt, Dc, Dc, 0, 0);
    transsplit<<<gW, tb>>>(wv, wvt, Dc, Dc, 0, 0);
    transsplit<<<gW, tb>>>(wo, wot, Dc, Dc, 0, 0);
    transsplit<<<gW, tb>>>(w1, w1t, Dc, Dc, 0, 0);
    transsplit<<<gW, tb>>>(w2, w2t, Dc, Dc, 0, 0);

    // 1) LN1 -> xn2 (split-A)
    layernorm_split<<<Mc, 256>>>(x, g1, be1, xn2);

    // 2) projections
    tgemm<E_SAB, false, false><<<gProj, 128, SMEM_SZ>>>(
        xn2, wqt, bq, nullptr, q2, Dc, Dc, 1.f, 0, 0, 0);
    tgemm<E_SBB, false, false><<<gProj, 128, SMEM_SZ>>>(
        xn2, wkt, bk, nullptr, k2, Dc, Dc, 1.f, 0, 0, 0);
    tgemm<E_FB, false, false><<<gProj, 128, SMEM_SZ>>>(
        xn2, wvt, bv, nullptr, v, Dc, Dc, 1.f, 0, 0, 0);

    // 3) v -> vt2 (transpose + split-B), per batch
    transsplit<<<gV, tb>>>(v, vt2, Sc, Dc, (long)Sc * Dc, (long)Dc * K3S);

    // 4) scores = (q k^T)/sqrt(S), causal tiles skipped
    tgemm<E_SC, true, false><<<gScore, 128, SMEM_SZ>>>(
        q2, k2, nullptr, nullptr, s, Dc, Sc, inv_sqrt_s, Sc, Sc, Sc);

    // 5) softmax -> a2 (split-A + zero pad)
    softmax_split<<<dim3(Sc, Bc), 256>>>(s, a2);

    // 6) attn @ V with block-K limit -> ao2 (split-A)
    tgemm<E_SA, false, true><<<gAV, 128, SMEM_SZ>>>(
        a2, vt2, nullptr, nullptr, ao2, Sc, Dc, 1.f, Sc, Dc, Sc);

    // 7) h = ao @ wo + bo + x
    tgemm<E_FBR, false, false><<<gProj, 128, SMEM_SZ>>>(
        ao2, wot, bo, x, h, Dc, Dc, 1.f, 0, 0, 0);

    // 8) LN2 -> m2 (split-A)
    layernorm_split<<<Mc, 256>>>(h, g2, be2, m2);

    // 9) f2 = relu(m @ w1 + b1) (split-A)
    tgemm<E_SABR, false, false><<<gProj, 128, SMEM_SZ>>>(
        m2, w1t, b1, nullptr, f2, Dc, Dc, 1.f, 0, 0, 0);

    // 10) out = f @ w2 + b2 + h
    tgemm<E_FBR, false, false><<<gProj, 128, SMEM_SZ>>>(
        f2, w2t, b2, h, out, Dc, Dc, 1.f, 0, 0, 0);
}

// round 6
// speedup vs baseline: 7.2858x; 2.5695x over previous
#include <cuda_runtime.h>
#include <cuda_fp16.h>
#include <math.h>
#include <stdint.h>

// ---------------- problem shape ----------------
#define Bc 4
#define Sc 2048
#define Dc 1024
#define Mc (Bc * Sc)

// ---------------- scratch (device globals; no allocation allowed) ----------
__device__ __align__(256) __half g_xn[(size_t)Mc * Dc];
__device__ __align__(256) __half g_q [(size_t)Mc * Dc];
__device__ __align__(256) __half g_k [(size_t)Mc * Dc];
__device__ __align__(256) __half g_v [(size_t)Mc * Dc];
__device__ __align__(256) __half g_vt[(size_t)Bc * Dc * Sc];
__device__ __align__(256) float  g_s [(size_t)Bc * Sc * Sc];
__device__ __align__(256) __half g_a [(size_t)Bc * Sc * Sc];
__device__ __align__(256) __half g_ao[(size_t)Mc * Dc];
__device__ __align__(256) float  g_h [(size_t)Mc * Dc];
__device__ __align__(256) __half g_m [(size_t)Mc * Dc];
__device__ __align__(256) __half g_f [(size_t)Mc * Dc];
__device__ __align__(256) __half g_wt[6][(size_t)Dc * Dc];

// ---------------- PTX helpers ----------------
__device__ __forceinline__ uint32_t s2u(const void* p) {
    uint32_t a;
    asm("{ .reg .u64 t; cvta.to.shared.u64 t, %1; cvt.u32.u64 %0, t; }"
        : "=r"(a) : "l"(p));
    return a;
}
__device__ __forceinline__ void cp16(uint32_t s, const void* g) {
    asm volatile("cp.async.cg.shared.global [%0], [%1], 16;" :: "r"(s), "l"(g));
}
#define CP_COMMIT() asm volatile("cp.async.commit_group;" ::: "memory")
#define CP_WAIT1()  asm volatile("cp.async.wait_group 1;" ::: "memory")

__device__ __forceinline__ void ldmat4(uint32_t (&r)[4], uint32_t addr) {
    asm volatile("ldmatrix.sync.aligned.m8n8.x4.shared.b16 {%0,%1,%2,%3}, [%4];"
                 : "=r"(r[0]), "=r"(r[1]), "=r"(r[2]), "=r"(r[3]) : "r"(addr));
}
__device__ __forceinline__ void mma16816(float (&d)[4], const uint32_t (&a)[4],
                                         const uint32_t b0, const uint32_t b1) {
    asm volatile(
        "mma.sync.aligned.m16n8k16.row.col.f32.f16.f16.f32 "
        "{%0,%1,%2,%3},{%4,%5,%6,%7},{%8,%9},{%0,%1,%2,%3};"
        : "+f"(d[0]), "+f"(d[1]), "+f"(d[2]), "+f"(d[3])
        : "r"(a[0]), "r"(a[1]), "r"(a[2]), "r"(a[3]), "r"(b0), "r"(b1));
}

// ---------------- fp16 mma GEMM (64x64 warp tile, 3-stage) ----------------
// C = alpha * A[M,K] (x) B[N,K]^T  (B given row-major as [N,K])
// EPI: 0=f32*alpha  2=f32+bias+res  7=h  8=h+bias  9=h+bias+relu
#define E_SC  0
#define E_FBR 2
#define E_H   7
#define E_HB  8
#define E_HBR 9

#define BKA 32          // K per stage (fp16)
#define SSTR 40         // padded smem row stride in halves (80 bytes)
#define STG_B (128 * SSTR * 2)       // one operand tile = 10240 B
#define STAGE_B (2 * STG_B)          // A+B per stage   = 20480 B
#define NSTG 3
#define SMEM_SZ (NSTG * STAGE_B)     // 61440 B

template <int EPI, bool CSKIP, bool CKLIM>
__global__ __launch_bounds__(128, 2)
void tgemm(const __half* __restrict__ A2, const __half* __restrict__ B2,
           const float* __restrict__ bias, const float* __restrict__ res,
           void* __restrict__ Cp, int Ksrc, int Nsrc, float alpha,
           long aRows, long bRows, long cRows)
{
    const int brow = blockIdx.y * 128;
    const int bcol = blockIdx.x * 128;
    if (CSKIP && bcol > brow + 127) return;
    const int z = blockIdx.z;

    extern __shared__ __align__(16) char smem[];
    const uint32_t sb = s2u(smem);

    const int tid = threadIdx.x;
    const int lane = tid & 31;
    const int w = tid >> 5;
    const int wm = (w & 1) * 64;
    const int wn = (w >> 1) * 64;

    const long lda = Ksrc;
    const __half* Arow = A2 + ((long)z * aRows + brow) * lda;
    const __half* Brow = B2 + ((long)z * bRows + bcol) * lda;

    const int nk = (CKLIM ? min(Ksrc, brow + 128) : Ksrc) / BKA;

    float acc[4][8][4];
#pragma unroll
    for (int i = 0; i < 4; ++i)
#pragma unroll
        for (int j = 0; j < 8; ++j)
#pragma unroll
            for (int u = 0; u < 4; ++u) acc[i][j][u] = 0.f;

    // loader: per stage, A and B are 128 rows x 32 halves (4 x 16B chunks/row)
    auto load_tile = [&](int t) {
        const int k0 = t * BKA;
        const uint32_t base = sb + (t % NSTG) * STAGE_B;
#pragma unroll
        for (int it = 0; it < 4; ++it) {
            const int idx = tid + it * 128;
            const int row = idx >> 2;
            const int ch  = idx & 3;
            const uint32_t off = row * (SSTR * 2) + ch * 16;
            cp16(base + off,         Arow + (long)row * lda + k0 + ch * 8);
            cp16(base + STG_B + off, Brow + (long)row * lda + k0 + ch * 8);
        }
    };

    const int a_moff = lane & 15;
    const int a_koff = (lane >> 4) * 8;
    const int b_noff = (lane & 7) + (lane >> 4) * 8;
    const int b_koff = ((lane >> 3) & 1) * 8;

    load_tile(0); CP_COMMIT();
    load_tile(1); CP_COMMIT();
    CP_WAIT1();
    __syncthreads();

    for (int t = 0; t < nk; ++t) {
        if (t + 2 < nk) load_tile(t + 2);
        CP_COMMIT();

        const uint32_t abase = sb + (t % NSTG) * STAGE_B;
        const uint32_t bbase = abase + STG_B;
#pragma unroll
        for (int ks = 0; ks < 2; ++ks) {
            uint32_t a[4][4];
#pragma unroll
            for (int mi = 0; mi < 4; ++mi)
                ldmat4(a[mi], abase + (uint32_t)((wm + mi * 16 + a_moff) * (SSTR * 2)
                                                 + (ks * 16 + a_koff) * 2));
            uint32_t b[8][2];
#pragma unroll
            for (int np = 0; np < 4; ++np) {
                uint32_t bb[4];
                ldmat4(bb, bbase + (uint32_t)((wn + np * 16 + b_noff) * (SSTR * 2)
                                              + (ks * 16 + b_koff) * 2));
                b[np * 2][0] = bb[0]; b[np * 2][1] = bb[1];
                b[np * 2 + 1][0] = bb[2]; b[np * 2 + 1][1] = bb[3];
            }
#pragma unroll
            for (int mi = 0; mi < 4; ++mi)
#pragma unroll
                for (int nj = 0; nj < 8; ++nj)
                    mma16816(acc[mi][nj], a[mi], b[nj][0], b[nj][1]);
        }
        CP_WAIT1();
        __syncthreads();
    }

    // ---------------- epilogue ----------------
#pragma unroll
    for (int mi = 0; mi < 4; ++mi) {
#pragma unroll
        for (int half_ = 0; half_ < 2; ++half_) {
            const int r = brow + wm + mi * 16 + (lane >> 2) + half_ * 8;
#pragma unroll
            for (int nj = 0; nj < 8; ++nj) {
                const int c = bcol + wn + nj * 8 + 2 * (lane & 3);
                float v0 = acc[mi][nj][half_ * 2 + 0] * alpha;
                float v1 = acc[mi][nj][half_ * 2 + 1] * alpha;

                if (EPI == E_SC || EPI == E_FBR) {
                    if (EPI == E_FBR) {
                        v0 += bias[c]; v1 += bias[c + 1];
                        const float2 rv = *reinterpret_cast<const float2*>(
                            res + (long)r * Nsrc + c);
                        v0 += rv.x; v1 += rv.y;
                    }
                    float2 o; o.x = v0; o.y = v1;
                    *reinterpret_cast<float2*>(
                        (float*)Cp + ((long)z * cRows + r) * (long)Nsrc + c) = o;
                } else {
                    if (EPI == E_HB || EPI == E_HBR) { v0 += bias[c]; v1 += bias[c + 1]; }
                    if (EPI == E_HBR) { v0 = fmaxf(v0, 0.f); v1 = fmaxf(v1, 0.f); }
                    __half2 o2 = __floats2half2_rn(v0, v1);
                    *reinterpret_cast<__half2*>(
                        (__half*)Cp + ((long)z * cRows + r) * (long)Nsrc + c) = o2;
                }
            }
        }
    }
}

// ---------------- LayerNorm -> fp16 output ----------------
__global__ __launch_bounds__(256)
void layernorm_h(const float* __restrict__ x, const float* __restrict__ gamma,
                 const float* __restrict__ beta, __half* __restrict__ y)
{
    const long rowi = blockIdx.x;
    const float* xr = x + rowi * Dc;
    __half* yr = y + rowi * Dc;
    __shared__ float red[256];
    const int tid = threadIdx.x;

    float s = 0.f;
    for (int i = tid; i < Dc; i += 256) s += xr[i];
    red[tid] = s; __syncthreads();
    for (int st = 128; st > 0; st >>= 1) {
        if (tid < st) red[tid] += red[tid + st];
        __syncthreads();
    }
    const float mean = red[0] / (float)Dc;
    __syncthreads();

    float v = 0.f;
    for (int i = tid; i < Dc; i += 256) {
        const float d = xr[i] - mean;
        v += d * d;
    }
    red[tid] = v; __syncthreads();
    for (int st = 128; st > 0; st >>= 1) {
        if (tid < st) red[tid] += red[tid + st];
        __syncthreads();
    }
    const float var = red[0] / (float)(Dc - 1);   // ddof=1
    const float inv = 1.f / (sqrtf(var) + 1e-6f); // eps on std

    for (int i = tid; i < Dc; i += 256)
        yr[i] = __float2half_rn(gamma[i] * (xr[i] - mean) * inv + beta[i]);
}

// ---------------- causal softmax -> fp16 (+zero pad to block) -------------
__global__ __launch_bounds__(256)
void softmax_h(const float* __restrict__ sc, __half* __restrict__ a)
{
    const int m = blockIdx.x;
    const int b = blockIdx.y;
    const float* row = sc + ((long)b * Sc + m) * (long)Sc;
    __half* orow = a + ((long)b * Sc + m) * (long)Sc;
    const int n = m + 1;
    __shared__ float red[256];
    const int tid = threadIdx.x;

    float lmax = -1e30f;
    for (int i = tid; i < n; i += 256) lmax = fmaxf(lmax, row[i]);
    red[tid] = lmax; __syncthreads();
    for (int st = 128; st > 0; st >>= 1) {
        if (tid < st) red[tid] = fmaxf(red[tid], red[tid + st]);
        __syncthreads();
    }
    const float gmax = red[0];
    __syncthreads();

    float lsum = 0.f;
    for (int i = tid; i < n; i += 256) lsum += __expf(row[i] - gmax);
    red[tid] = lsum; __syncthreads();
    for (int st = 128; st > 0; st >>= 1) {
        if (tid < st) red[tid] += red[tid + st];
        __syncthreads();
    }
    const float inv = 1.f / red[0];

    for (int i = tid; i < n; i += 256)
        orow[i] = __float2half_rn(__expf(row[i] - gmax) * inv);
    // zero-fill (m, m|127] so the AV block-K-limit reads zeros
    const int lim = (m | 127);
    for (int i = n + tid; i <= lim; i += 256) orow[i] = __float2half_rn(0.f);
}

// ---------------- transpose f32 -> fp16 (weights) ----------------
// src fp32 [R, C] -> dst fp16 [C, R]
__global__ __launch_bounds__(256)
void trans_f2h(const float* __restrict__ src, __half* __restrict__ dst, int R, int C)
{
    __shared__ float t[32][33];
    const int c0 = blockIdx.x * 32;
    const int r0 = blockIdx.y * 32;
    const int tx = threadIdx.x, ty = threadIdx.y;  // 32 x 8

#pragma unroll
    for (int i = 0; i < 4; ++i)
        t[ty + 8 * i][tx] = src[(long)(r0 + ty + 8 * i) * C + c0 + tx];
    __syncthreads();

#pragma unroll
    for (int i = 0; i < 4; ++i) {
        const int c = c0 + ty + 8 * i;
        const int r = r0 + tx;
        dst[(long)c * R + r] = __float2half_rn(t[tx][ty + 8 * i]);
    }
}

// ---------------- transpose fp16 -> fp16 (V), per batch ----------------
// src fp16 [R, C] -> dst fp16 [C, R]
__global__ __launch_bounds__(256)
void trans_h2h(const __half* __restrict__ src, __half* __restrict__ dst,
               int R, int C, long srcBatch, long dstBatch)
{
    const int zb = blockIdx.z;
    src += (long)zb * srcBatch;
    dst += (long)zb * dstBatch;
    __shared__ __half t[32][34];
    const int c0 = blockIdx.x * 32;
    const int r0 = blockIdx.y * 32;
    const int tx = threadIdx.x, ty = threadIdx.y;

#pragma unroll
    for (int i = 0; i < 4; ++i)
        t[ty + 8 * i][tx] = src[(long)(r0 + ty + 8 * i) * C + c0 + tx];
    __syncthreads();

#pragma unroll
    for (int i = 0; i < 4; ++i) {
        const int c = c0 + ty + 8 * i;
        const int r = r0 + tx;
        dst[(long)c * R + r] = t[tx][ty + 8 * i];
    }
}

// ---------------------------------------------------------------------------
extern "C" void kernel_launch(void* const* d_in, const int* in_sizes, int n_in,
                              void* d_out, int out_size)
{
    const float* x   = (const float*)d_in[0];
    const float* wq  = (const float*)d_in[1];
    const float* bq  = (const float*)d_in[2];
    const float* wk  = (const float*)d_in[3];
    const float* bk  = (const float*)d_in[4];
    const float* wv  = (const float*)d_in[5];
    const float* bv  = (const float*)d_in[6];
    const float* wo  = (const float*)d_in[7];
    const float* bo  = (const float*)d_in[8];
    const float* w1  = (const float*)d_in[9];
    const float* b1  = (const float*)d_in[10];
    const float* w2  = (const float*)d_in[11];
    const float* b2  = (const float*)d_in[12];
    const float* g1  = (const float*)d_in[13];
    const float* be1 = (const float*)d_in[14];
    const float* g2  = (const float*)d_in[15];
    const float* be2 = (const float*)d_in[16];
    float* out = (float*)d_out;

    __half *xn, *q, *k, *v, *vt, *a, *ao, *m, *f, *wt;
    float *s, *h;
    cudaGetSymbolAddress((void**)&xn, g_xn);
    cudaGetSymbolAddress((void**)&q,  g_q);
    cudaGetSymbolAddress((void**)&k,  g_k);
    cudaGetSymbolAddress((void**)&v,  g_v);
    cudaGetSymbolAddress((void**)&vt, g_vt);
    cudaGetSymbolAddress((void**)&s,  g_s);
    cudaGetSymbolAddress((void**)&a,  g_a);
    cudaGetSymbolAddress((void**)&ao, g_ao);
    cudaGetSymbolAddress((void**)&h,  g_h);
    cudaGetSymbolAddress((void**)&m,  g_m);
    cudaGetSymbolAddress((void**)&f,  g_f);
    cudaGetSymbolAddress((void**)&wt, g_wt);

    __half* wqt = wt + 0L * Dc * Dc;
    __half* wkt = wt + 1L * Dc * Dc;
    __half* wvt = wt + 2L * Dc * Dc;
    __half* wot = wt + 3L * Dc * Dc;
    __half* w1t = wt + 4L * Dc * Dc;
    __half* w2t = wt + 5L * Dc * Dc;

    cudaFuncSetAttribute((const void*)tgemm<E_HB,  false, false>, cudaFuncAttributeMaxDynamicSharedMemorySize, SMEM_SZ);
    cudaFuncSetAttribute((const void*)tgemm<E_SC,  true,  false>, cudaFuncAttributeMaxDynamicSharedMemorySize, SMEM_SZ);
    cudaFuncSetAttribute((const void*)tgemm<E_H,   false, true >, cudaFuncAttributeMaxDynamicSharedMemorySize, SMEM_SZ);
    cudaFuncSetAttribute((const void*)tgemm<E_FBR, false, false>, cudaFuncAttributeMaxDynamicSharedMemorySize, SMEM_SZ);
    cudaFuncSetAttribute((const void*)tgemm<E_HBR, false, false>, cudaFuncAttributeMaxDynamicSharedMemorySize, SMEM_SZ);

    const float inv_sqrt_s = 1.0f / sqrtf((float)Sc);
    const dim3 tb(32, 8);
    const dim3 gW(Dc / 32, Dc / 32, 1);
    const dim3 gV(Dc / 32, Sc / 32, Bc);
    const dim3 gProj(Dc / 128, Mc / 128, 1);     // 8 x 64
    const dim3 gScore(Sc / 128, Sc / 128, Bc);   // 16 x 16 x 4
    const dim3 gAV(Dc / 128, Sc / 128, Bc);      // 8 x 16 x 4

    // weight transposes -> fp16 [N, K]
    trans_f2h<<<gW, tb>>>(wq, wqt, Dc, Dc);
    trans_f2h<<<gW, tb>>>(wk, wkt, Dc, Dc);
    trans_f2h<<<gW, tb>>>(wv, wvt, Dc, Dc);
    trans_f2h<<<gW, tb>>>(wo, wot, Dc, Dc);
    trans_f2h<<<gW, tb>>>(w1, w1t, Dc, Dc);
    trans_f2h<<<gW, tb>>>(w2, w2t, Dc, Dc);

    // 1) LN1 -> xn (fp16)
    layernorm_h<<<Mc, 256>>>(x, g1, be1, xn);

    // 2) projections (fp16 out, bias fused)
    tgemm<E_HB, false, false><<<gProj, 128, SMEM_SZ>>>(
        xn, wqt, bq, nullptr, q, Dc, Dc, 1.f, 0, 0, 0);
    tgemm<E_HB, false, false><<<gProj, 128, SMEM_SZ>>>(
        xn, wkt, bk, nullptr, k, Dc, Dc, 1.f, 0, 0, 0);
    tgemm<E_HB, false, false><<<gProj, 128, SMEM_SZ>>>(
        xn, wvt, bv, nullptr, v, Dc, Dc, 1.f, 0, 0, 0);

    // 3) v -> vt (transpose per batch)
    trans_h2h<<<gV, tb>>>(v, vt, Sc, Dc, (long)Sc * Dc, (long)Dc * Sc);

    // 4) scores = (q k^T)/sqrt(S), causal tiles skipped (f32 out)
    tgemm<E_SC, true, false><<<gScore, 128, SMEM_SZ>>>(
        q, k, nullptr, nullptr, s, Dc, Sc, inv_sqrt_s, Sc, Sc, Sc);

    // 5) softmax -> a (fp16 + zero pad)
    softmax_h<<<dim3(Sc, Bc), 256>>>(s, a);

    // 6) attn @ V with block-K limit -> ao (fp16)
    tgemm<E_H, false, true><<<gAV, 128, SMEM_SZ>>>(
        a, vt, nullptr, nullptr, ao, Sc, Dc, 1.f, Sc, Dc, Sc);

    // 7) h = ao @ wo + bo + x (f32)
    tgemm<E_FBR, false, false><<<gProj, 128, SMEM_SZ>>>(
        ao, wot, bo, x, h, Dc, Dc, 1.f, 0, 0, 0);

    // 8) LN2 -> m (fp16)
    layernorm_h<<<Mc, 256>>>(h, g2, be2, m);

    // 9) f = relu(m @ w1 + b1) (fp16)
    tgemm<E_HBR, false, false><<<gProj, 128, SMEM_SZ>>>(
        m, w1t, b1, nullptr, f, Dc, Dc, 1.f, 0, 0, 0);

    // 10) out = f @ w2 + b2 + h (f32)
    tgemm<E_FBR, false, false><<<gProj, 128, SMEM_SZ>>>(
        f, w2t, b2, h, out, Dc, Dc, 1.f, 0, 0, 0);
}

// round 8
// speedup vs baseline: 7.2904x; 1.0006x over previous
#include <cuda_runtime.h>
#include <cuda_fp16.h>
#include <math.h>
#include <stdint.h>

// ---------------- problem shape ----------------
#define Bc 4
#define Sc 2048
#define Dc 1024
#define Mc (Bc * Sc)
#define D3 (3 * Dc)

// ---------------- scratch (device globals; no allocation allowed) ----------
__device__ __align__(256) __half g_xn  [(size_t)Mc * Dc];
__device__ __align__(256) __half g_qkv [(size_t)Mc * D3];
__device__ __align__(256) __half g_vt  [(size_t)Bc * Dc * Sc];
__device__ __align__(256) float  g_s   [(size_t)Bc * Sc * Sc];
__device__ __align__(256) __half g_a   [(size_t)Bc * Sc * Sc];
__device__ __align__(256) __half g_ao  [(size_t)Mc * Dc];
__device__ __align__(256) float  g_h   [(size_t)Mc * Dc];
__device__ __align__(256) __half g_m   [(size_t)Mc * Dc];
__device__ __align__(256) __half g_f   [(size_t)Mc * Dc];
__device__ __align__(256) __half g_wt  [6][(size_t)Dc * Dc];
__device__ __align__(256) float  g_bqkv[D3];

// ---------------- PTX helpers ----------------
__device__ __forceinline__ uint32_t s2u(const void* p) {
    uint32_t a;
    asm("{ .reg .u64 t; cvta.to.shared.u64 t, %1; cvt.u32.u64 %0, t; }"
        : "=r"(a) : "l"(p));
    return a;
}
__device__ __forceinline__ void cp16(uint32_t s, const void* g) {
    asm volatile("cp.async.cg.shared.global [%0], [%1], 16;" :: "r"(s), "l"(g));
}
#define CP_COMMIT() asm volatile("cp.async.commit_group;" ::: "memory")
#define CP_WAIT1()  asm volatile("cp.async.wait_group 1;" ::: "memory")

__device__ __forceinline__ void ldmat4(uint32_t (&r)[4], uint32_t addr) {
    asm volatile("ldmatrix.sync.aligned.m8n8.x4.shared.b16 {%0,%1,%2,%3}, [%4];"
                 : "=r"(r[0]), "=r"(r[1]), "=r"(r[2]), "=r"(r[3]) : "r"(addr));
}
__device__ __forceinline__ void mma16816(float (&d)[4], const uint32_t (&a)[4],
                                         const uint32_t b0, const uint32_t b1) {
    asm volatile(
        "mma.sync.aligned.m16n8k16.row.col.f32.f16.f16.f32 "
        "{%0,%1,%2,%3},{%4,%5,%6,%7},{%8,%9},{%0,%1,%2,%3};"
        : "+f"(d[0]), "+f"(d[1]), "+f"(d[2]), "+f"(d[3])
        : "r"(a[0]), "r"(a[1]), "r"(a[2]), "r"(a[3]), "r"(b0), "r"(b1));
}

// ---------------- fp16 mma GEMM (64x64 warp tile, 3-stage, BK=64) ----------
// C = alpha * A[.,K] (x) B[.,K]^T    (both operands row-major over K, strided)
// EPI: 0=f32*alpha  2=f32+bias+res  7=h  8=h+bias  9=h+bias+relu
#define E_SC  0
#define E_FBR 2
#define E_H   7
#define E_HB  8
#define E_HBR 9

#define BKA 64                         // K per stage (fp16)
#define SSTR 72                        // padded smem row stride in halves (144 B)
#define STG_B (128 * SSTR * 2)         // one operand tile = 18432 B
#define STAGE_B (2 * STG_B)            // A+B per stage   = 36864 B
#define NSTG 3
#define SMEM_SZ (NSTG * STAGE_B)       // 110592 B

template <int EPI, bool CSKIP, bool CKLIM>
__global__ __launch_bounds__(128, 2)
void tgemm(const __half* __restrict__ A2, const __half* __restrict__ B2,
           const float* __restrict__ bias, const float* __restrict__ res,
           void* __restrict__ Cp, int Ksrc, int Nsrc, float alpha,
           long aRows, long bRows, long cRows, int lda, int ldb)
{
    const int brow = blockIdx.y * 128;
    const int bcol = blockIdx.x * 128;
    if (CSKIP && bcol > brow + 127) return;
    const int z = blockIdx.z;

    extern __shared__ __align__(16) char smem[];
    const uint32_t sb = s2u(smem);

    const int tid = threadIdx.x;
    const int lane = tid & 31;
    const int w = tid >> 5;
    const int wm = (w & 1) * 64;
    const int wn = (w >> 1) * 64;

    const __half* Arow = A2 + ((long)z * aRows + brow) * (long)lda;
    const __half* Brow = B2 + ((long)z * bRows + bcol) * (long)ldb;

    const int nk = (CKLIM ? min(Ksrc, brow + 128) : Ksrc) / BKA;

    float acc[4][8][4];
#pragma unroll
    for (int i = 0; i < 4; ++i)
#pragma unroll
        for (int j = 0; j < 8; ++j)
#pragma unroll
            for (int u = 0; u < 4; ++u) acc[i][j][u] = 0.f;

    // loader: per stage, A and B are 128 rows x 64 halves (8 x 16B chunks/row)
    auto load_tile = [&](int t) {
        const int k0 = t * BKA;
        const uint32_t base = sb + (t % NSTG) * STAGE_B;
#pragma unroll
        for (int it = 0; it < 8; ++it) {
            const int idx = tid + it * 128;
            const int row = idx >> 3;
            const int ch  = idx & 7;
            const uint32_t off = row * (SSTR * 2) + ch * 16;
            cp16(base + off,         Arow + (long)row * lda + k0 + ch * 8);
            cp16(base + STG_B + off, Brow + (long)row * ldb + k0 + ch * 8);
        }
    };

    const int a_moff = lane & 15;
    const int a_koff = (lane >> 4) * 8;
    const int b_noff = (lane & 7) + (lane >> 4) * 8;
    const int b_koff = ((lane >> 3) & 1) * 8;

    load_tile(0); CP_COMMIT();
    load_tile(1); CP_COMMIT();
    CP_WAIT1();
    __syncthreads();

    for (int t = 0; t < nk; ++t) {
        if (t + 2 < nk) load_tile(t + 2);
        CP_COMMIT();

        const uint32_t abase = sb + (t % NSTG) * STAGE_B;
        const uint32_t bbase = abase + STG_B;
#pragma unroll
        for (int ks = 0; ks < 4; ++ks) {
            uint32_t a[4][4];
#pragma unroll
            for (int mi = 0; mi < 4; ++mi)
                ldmat4(a[mi], abase + (uint32_t)((wm + mi * 16 + a_moff) * (SSTR * 2)
                                                 + (ks * 16 + a_koff) * 2));
            uint32_t b[8][2];
#pragma unroll
            for (int np = 0; np < 4; ++np) {
                uint32_t bb[4];
                ldmat4(bb, bbase + (uint32_t)((wn + np * 16 + b_noff) * (SSTR * 2)
                                              + (ks * 16 + b_koff) * 2));
                b[np * 2][0] = bb[0]; b[np * 2][1] = bb[1];
                b[np * 2 + 1][0] = bb[2]; b[np * 2 + 1][1] = bb[3];
            }
#pragma unroll
            for (int mi = 0; mi < 4; ++mi)
#pragma unroll
                for (int nj = 0; nj < 8; ++nj)
                    mma16816(acc[mi][nj], a[mi], b[nj][0], b[nj][1]);
        }
        CP_WAIT1();
        __syncthreads();
    }

    // ---------------- epilogue ----------------
#pragma unroll
    for (int mi = 0; mi < 4; ++mi) {
#pragma unroll
        for (int half_ = 0; half_ < 2; ++half_) {
            const int r = brow + wm + mi * 16 + (lane >> 2) + half_ * 8;
#pragma unroll
            for (int nj = 0; nj < 8; ++nj) {
                const int c = bcol + wn + nj * 8 + 2 * (lane & 3);
                float v0 = acc[mi][nj][half_ * 2 + 0] * alpha;
                float v1 = acc[mi][nj][half_ * 2 + 1] * alpha;

                if (EPI == E_SC || EPI == E_FBR) {
                    if (EPI == E_FBR) {
                        v0 += bias[c]; v1 += bias[c + 1];
                        const float2 rv = *reinterpret_cast<const float2*>(
                            res + (long)r * Nsrc + c);
                        v0 += rv.x; v1 += rv.y;
                    }
                    float2 o; o.x = v0; o.y = v1;
                    *reinterpret_cast<float2*>(
                        (float*)Cp + ((long)z * cRows + r) * (long)Nsrc + c) = o;
                } else {
                    if (EPI == E_HB || EPI == E_HBR) { v0 += bias[c]; v1 += bias[c + 1]; }
                    if (EPI == E_HBR) { v0 = fmaxf(v0, 0.f); v1 = fmaxf(v1, 0.f); }
                    __half2 o2 = __floats2half2_rn(v0, v1);
                    *reinterpret_cast<__half2*>(
                        (__half*)Cp + ((long)z * cRows + r) * (long)Nsrc + c) = o2;
                }
            }
        }
    }
}

// ---------------- LayerNorm -> fp16 output (vectorized) ----------------
__global__ __launch_bounds__(256)
void layernorm_h(const float* __restrict__ x, const float* __restrict__ gamma,
                 const float* __restrict__ beta, __half* __restrict__ y)
{
    const long rowi = blockIdx.x;
    const int tid = threadIdx.x;
    const int lane = tid & 31;
    const int wid = tid >> 5;
    __shared__ float ws[8];

    const float4 xv = reinterpret_cast<const float4*>(x + rowi * Dc)[tid];

    float s = xv.x + xv.y + xv.z + xv.w;
#pragma unroll
    for (int o = 16; o > 0; o >>= 1) s += __shfl_xor_sync(0xffffffffu, s, o);
    if (lane == 0) ws[wid] = s;
    __syncthreads();
    float tot = 0.f;
#pragma unroll
    for (int i = 0; i < 8; ++i) tot += ws[i];
    const float mean = tot * (1.f / (float)Dc);
    __syncthreads();

    const float d0 = xv.x - mean, d1 = xv.y - mean, d2 = xv.z - mean, d3 = xv.w - mean;
    float v = d0 * d0 + d1 * d1 + d2 * d2 + d3 * d3;
#pragma unroll
    for (int o = 16; o > 0; o >>= 1) v += __shfl_xor_sync(0xffffffffu, v, o);
    if (lane == 0) ws[wid] = v;
    __syncthreads();
    float vtot = 0.f;
#pragma unroll
    for (int i = 0; i < 8; ++i) vtot += ws[i];
    const float var = vtot * (1.f / (float)(Dc - 1));   // ddof=1
    const float inv = 1.f / (sqrtf(var) + 1e-6f);       // eps on std

    const float4 gv = reinterpret_cast<const float4*>(gamma)[tid];
    const float4 bv = reinterpret_cast<const float4*>(beta)[tid];
    const float r0 = gv.x * d0 * inv + bv.x;
    const float r1 = gv.y * d1 * inv + bv.y;
    const float r2 = gv.z * d2 * inv + bv.z;
    const float r3 = gv.w * d3 * inv + bv.w;

    __half2* yr = reinterpret_cast<__half2*>(y + rowi * Dc);
    yr[2 * tid]     = __floats2half2_rn(r0, r1);
    yr[2 * tid + 1] = __floats2half2_rn(r2, r3);
}

// ---------------- causal softmax -> fp16 (+zero pad to block) -------------
__global__ __launch_bounds__(256)
void softmax_h(const float* __restrict__ sc, __half* __restrict__ a)
{
    const int m = blockIdx.x;
    const int b = blockIdx.y;
    const float* row = sc + ((long)b * Sc + m) * (long)Sc;
    __half* orow = a + ((long)b * Sc + m) * (long)Sc;
    const int n = m + 1;
    __shared__ float red[256];
    const int tid = threadIdx.x;

    float lmax = -1e30f;
    for (int i = tid; i < n; i += 256) lmax = fmaxf(lmax, row[i]);
    red[tid] = lmax; __syncthreads();
    for (int st = 128; st > 0; st >>= 1) {
        if (tid < st) red[tid] = fmaxf(red[tid], red[tid + st]);
        __syncthreads();
    }
    const float gmax = red[0];
    __syncthreads();

    float lsum = 0.f;
    for (int i = tid; i < n; i += 256) lsum += __expf(row[i] - gmax);
    red[tid] = lsum; __syncthreads();
    for (int st = 128; st > 0; st >>= 1) {
        if (tid < st) red[tid] += red[tid + st];
        __syncthreads();
    }
    const float inv = 1.f / red[0];

    for (int i = tid; i < n; i += 256)
        orow[i] = __float2half_rn(__expf(row[i] - gmax) * inv);
    const int lim = (m | 127);
    for (int i = n + tid; i <= lim; i += 256) orow[i] = __float2half_rn(0.f);
}

// ---------------- transpose f32 -> fp16 (weights) ----------------
__global__ __launch_bounds__(256)
void trans_f2h(const float* __restrict__ src, __half* __restrict__ dst, int R, int C)
{
    __shared__ float t[32][33];
    const int c0 = blockIdx.x * 32;
    const int r0 = blockIdx.y * 32;
    const int tx = threadIdx.x, ty = threadIdx.y;  // 32 x 8

#pragma unroll
    for (int i = 0; i < 4; ++i)
        t[ty + 8 * i][tx] = src[(long)(r0 + ty + 8 * i) * C + c0 + tx];
    __syncthreads();

#pragma unroll
    for (int i = 0; i < 4; ++i) {
        const int c = c0 + ty + 8 * i;
        const int r = r0 + tx;
        dst[(long)c * R + r] = __float2half_rn(t[tx][ty + 8 * i]);
    }
}

// ---------------- transpose fp16 -> fp16 (V slice of qkv), per batch -------
// src: [R rows, stride srcStride], dst: [C, R]
__global__ __launch_bounds__(256)
void trans_h2h(const __half* __restrict__ src, __half* __restrict__ dst,
               int R, int C, int srcStride, long srcBatch, long dstBatch)
{
    const int zb = blockIdx.z;
    src += (long)zb * srcBatch;
    dst += (long)zb * dstBatch;
    __shared__ __half t[32][34];
    const int c0 = blockIdx.x * 32;
    const int r0 = blockIdx.y * 32;
    const int tx = threadIdx.x, ty = threadIdx.y;

#pragma unroll
    for (int i = 0; i < 4; ++i)
        t[ty + 8 * i][tx] = src[(long)(r0 + ty + 8 * i) * srcStride + c0 + tx];
    __syncthreads();

#pragma unroll
    for (int i = 0; i < 4; ++i) {
        const int c = c0 + ty + 8 * i;
        const int r = r0 + tx;
        dst[(long)c * R + r] = t[tx][ty + 8 * i];
    }
}

// ---------------- bias concat ----------------
__global__ __launch_bounds__(256)
void concat_bias(const float* __restrict__ bq, const float* __restrict__ bk,
                 const float* __restrict__ bv, float* __restrict__ o)
{
    const int i = blockIdx.x * 256 + threadIdx.x;
    if (i < Dc) {
        o[i] = bq[i];
        o[Dc + i] = bk[i];
        o[2 * Dc + i] = bv[i];
    }
}

// ---------------------------------------------------------------------------
extern "C" void kernel_launch(void* const* d_in, const int* in_sizes, int n_in,
                              void* d_out, int out_size)
{
    const float* x   = (const float*)d_in[0];
    const float* wq  = (const float*)d_in[1];
    const float* bq  = (const float*)d_in[2];
    const float* wk  = (const float*)d_in[3];
    const float* bk  = (const float*)d_in[4];
    const float* wv  = (const float*)d_in[5];
    const float* bv  = (const float*)d_in[6];
    const float* wo  = (const float*)d_in[7];
    const float* bo  = (const float*)d_in[8];
    const float* w1  = (const float*)d_in[9];
    const float* b1  = (const float*)d_in[10];
    const float* w2  = (const float*)d_in[11];
    const float* b2  = (const float*)d_in[12];
    const float* g1  = (const float*)d_in[13];
    const float* be1 = (const float*)d_in[14];
    const float* g2  = (const float*)d_in[15];
    const float* be2 = (const float*)d_in[16];
    float* out = (float*)d_out;

    __half *xn, *qkv, *vt, *a, *ao, *m, *f, *wt;
    float *s, *h, *bqkv;
    cudaGetSymbolAddress((void**)&xn,  g_xn);
    cudaGetSymbolAddress((void**)&qkv, g_qkv);
    cudaGetSymbolAddress((void**)&vt,  g_vt);
    cudaGetSymbolAddress((void**)&s,   g_s);
    cudaGetSymbolAddress((void**)&a,   g_a);
    cudaGetSymbolAddress((void**)&ao,  g_ao);
    cudaGetSymbolAddress((void**)&h,   g_h);
    cudaGetSymbolAddress((void**)&m,   g_m);
    cudaGetSymbolAddress((void**)&f,   g_f);
    cudaGetSymbolAddress((void**)&wt,  g_wt);
    cudaGetSymbolAddress((void**)&bqkv, g_bqkv);

    __half* wqt = wt + 0L * Dc * Dc;   // rows 0..1023   of QKV B operand
    __half* wkt = wt + 1L * Dc * Dc;   // rows 1024..2047
    __half* wvt = wt + 2L * Dc * Dc;   // rows 2048..3071
    __half* wot = wt + 3L * Dc * Dc;
    __half* w1t = wt + 4L * Dc * Dc;
    __half* w2t = wt + 5L * Dc * Dc;

    cudaFuncSetAttribute((const void*)tgemm<E_HB,  false, false>, cudaFuncAttributeMaxDynamicSharedMemorySize, SMEM_SZ);
    cudaFuncSetAttribute((const void*)tgemm<E_SC,  true,  false>, cudaFuncAttributeMaxDynamicSharedMemorySize, SMEM_SZ);
    cudaFuncSetAttribute((const void*)tgemm<E_H,   false, true >, cudaFuncAttributeMaxDynamicSharedMemorySize, SMEM_SZ);
    cudaFuncSetAttribute((const void*)tgemm<E_FBR, false, false>, cudaFuncAttributeMaxDynamicSharedMemorySize, SMEM_SZ);
    cudaFuncSetAttribute((const void*)tgemm<E_HBR, false, false>, cudaFuncAttributeMaxDynamicSharedMemorySize, SMEM_SZ);

    const float inv_sqrt_s = 1.0f / sqrtf((float)Sc);
    const dim3 tb(32, 8);
    const dim3 gW(Dc / 32, Dc / 32, 1);
    const dim3 gV(Dc / 32, Sc / 32, Bc);
    const dim3 gQKV(D3 / 128, Mc / 128, 1);      // 24 x 64
    const dim3 gProj(Dc / 128, Mc / 128, 1);     // 8 x 64
    const dim3 gScore(Sc / 128, Sc / 128, Bc);   // 16 x 16 x 4
    const dim3 gAV(Dc / 128, Sc / 128, Bc);      // 8 x 16 x 4

    // weight transposes -> fp16 [N, K] (QKV contiguous in g_wt)
    trans_f2h<<<gW, tb>>>(wq, wqt, Dc, Dc);
    trans_f2h<<<gW, tb>>>(wk, wkt, Dc, Dc);
    trans_f2h<<<gW, tb>>>(wv, wvt, Dc, Dc);
    trans_f2h<<<gW, tb>>>(wo, wot, Dc, Dc);
    trans_f2h<<<gW, tb>>>(w1, w1t, Dc, Dc);
    trans_f2h<<<gW, tb>>>(w2, w2t, Dc, Dc);
    concat_bias<<<4, 256>>>(bq, bk, bv, bqkv);

    // 1) LN1 -> xn (fp16)
    layernorm_h<<<Mc, 256>>>(x, g1, be1, xn);

    // 2) fused QKV projection: [M,1024] @ [3072,1024]^T -> [M,3072] fp16
    tgemm<E_HB, false, false><<<gQKV, 128, SMEM_SZ>>>(
        xn, wt, bqkv, nullptr, qkv, Dc, D3, 1.f, 0, 0, 0, Dc, Dc);

    // 3) v slice -> vt (transpose per batch)
    trans_h2h<<<gV, tb>>>(qkv + 2 * Dc, vt, Sc, Dc, D3,
                          (long)Sc * D3, (long)Dc * Sc);

    // 4) scores = (q k^T)/sqrt(S), causal tiles skipped (f32 out)
    tgemm<E_SC, true, false><<<gScore, 128, SMEM_SZ>>>(
        qkv, qkv + Dc, nullptr, nullptr, s, Dc, Sc, inv_sqrt_s,
        Sc, Sc, Sc, D3, D3);

    // 5) softmax -> a (fp16 + zero pad)
    softmax_h<<<dim3(Sc, Bc), 256>>>(s, a);

    // 6) attn @ V with block-K limit -> ao (fp16)
    tgemm<E_H, false, true><<<gAV, 128, SMEM_SZ>>>(
        a, vt, nullptr, nullptr, ao, Sc, Dc, 1.f, Sc, Dc, Sc, Sc, Sc);

    // 7) h = ao @ wo + bo + x (f32)
    tgemm<E_FBR, false, false><<<gProj, 128, SMEM_SZ>>>(
        ao, wot, bo, x, h, Dc, Dc, 1.f, 0, 0, 0, Dc, Dc);

    // 8) LN2 -> m (fp16)
    layernorm_h<<<Mc, 256>>>(h, g2, be2, m);

    // 9) f = relu(m @ w1 + b1) (fp16)
    tgemm<E_HBR, false, false><<<gProj, 128, SMEM_SZ>>>(
        m, w1t, b1, nullptr, f, Dc, Dc, 1.f, 0, 0, 0, Dc, Dc);

    // 10) out = f @ w2 + b2 + h (f32)
    tgemm<E_FBR, false, false><<<gProj, 128, SMEM_SZ>>>(
        f, w2t, b2, h, out, Dc, Dc, 1.f, 0, 0, 0, Dc, Dc);
}